// round 5
// baseline (speedup 1.0000x reference)
#include <cuda_runtime.h>
#include <math.h>

#define Bn 64
#define Nn 128
#define Dn 32
#define Gn 127              // N-1
#define Pn (Nn*(Nn-1))      // 16256
#define HFn 16
#define EPSf 1e-5f

typedef unsigned long long u64;

// ---------------- scratch (static device globals; no allocation) -------------
__device__ float g_U[Bn*Nn*Dn];      // U'[b][n][c] = x@W1_top + b1
__device__ float g_V[Bn*Nn*Dn];      // V [b][n][c] = x@W1_bot
__device__ float g_sumU[Nn], g_sumU2[Nn], g_sumV[Nn], g_sumV2[Nn];
__device__ float g_C[Nn*Nn];         // C[s][t] = sum_{b,c} U'[b,s,c]*V[b,t,c]
__device__ float g_f[Bn*Nn*HFn];     // pre-LN features of final MLP
__device__ float g_part[64*32];      // kE1 partials
__device__ float g_lnp[2*HFn];       // [0:16) scale, [16:32) shift

__device__ __forceinline__ float leaky(float x) { return x > 0.f ? x : 0.01f * x; }

// packed f32x2 helpers
__device__ __forceinline__ u64 pk2(float lo, float hi) {
    u64 r;
    asm("mov.b64 %0, {%1, %2};" : "=l"(r) : "r"(__float_as_uint(lo)), "r"(__float_as_uint(hi)));
    return r;
}
__device__ __forceinline__ float hadd2(u64 v) {
    unsigned lo, hi;
    asm("mov.b64 {%0, %1}, %2;" : "=r"(lo), "=r"(hi) : "l"(v));
    return __uint_as_float(lo) + __uint_as_float(hi);
}
__device__ __forceinline__ u64 ffma2(u64 a, u64 b, u64 c) {
    u64 d;
    asm("fma.rn.f32x2 %0, %1, %2, %3;" : "=l"(d) : "l"(a), "l"(b), "l"(c));
    return d;
}

// ---------------- Kernel A: per-node projections + per-node stats ------------
// grid = N, block = 64 (one thread per batch element)
__global__ void kA(const float* __restrict__ inp, const float* __restrict__ W1,
                   const float* __restrict__ b1) {
    const int n = blockIdx.x;
    const int b = threadIdx.x;     // 0..63
    __shared__ __align__(16) float W1t[32*64];   // W1t[c*64 + k] = W1[k*32 + c]
    __shared__ float red[64*4];
    for (int idx = b; idx < 2048; idx += 64) {
        int k = idx & 63, c = idx >> 6;
        W1t[c*64 + k] = W1[k*32 + c];
    }
    __syncthreads();

    float x[32];
    const float4* xp = (const float4*)(inp + ((size_t)b*Nn + n)*Dn);
    #pragma unroll
    for (int q = 0; q < 8; q++) {
        float4 v = xp[q];
        x[4*q+0]=v.x; x[4*q+1]=v.y; x[4*q+2]=v.z; x[4*q+3]=v.w;
    }
    float su=0.f, su2=0.f, sv=0.f, sv2=0.f;
    float* Uo = g_U + ((size_t)b*Nn + n)*Dn;
    float* Vo = g_V + ((size_t)b*Nn + n)*Dn;
    #pragma unroll 4
    for (int c = 0; c < 32; c++) {
        const float4* wr = (const float4*)(W1t + c*64);
        float u = b1[c];
        float v = 0.f;
        #pragma unroll
        for (int j = 0; j < 8; j++) {
            float4 wu = wr[j];
            float4 wv = wr[8 + j];
            u += x[4*j+0]*wu.x + x[4*j+1]*wu.y + x[4*j+2]*wu.z + x[4*j+3]*wu.w;
            v += x[4*j+0]*wv.x + x[4*j+1]*wv.y + x[4*j+2]*wv.z + x[4*j+3]*wv.w;
        }
        Uo[c] = u; Vo[c] = v;
        su += u; su2 += u*u; sv += v; sv2 += v*v;
    }
    red[b] = su; red[64+b] = su2; red[128+b] = sv; red[192+b] = sv2;
    __syncthreads();
    for (int s = 32; s > 0; s >>= 1) {
        if (b < s) {
            red[b]     += red[b+s];
            red[64+b]  += red[64+b+s];
            red[128+b] += red[128+b+s];
            red[192+b] += red[192+b+s];
        }
        __syncthreads();
    }
    if (b == 0) {
        g_sumU[n]  = red[0];
        g_sumU2[n] = red[64];
        g_sumV[n]  = red[128];
        g_sumV2[n] = red[192];
    }
}

// ---------------- Kernel B: cross term C[s,t], 128x128, K = 64*32 ------------
// grid = (8,8), block = 256 (16x16 tile)
__global__ void kB() {
    const int t0 = blockIdx.x * 16;
    const int s0 = blockIdx.y * 16;
    const int tx = threadIdx.x & 15;
    const int ty = threadIdx.x >> 4;
    __shared__ __align__(16) float Us[16][36];
    __shared__ __align__(16) float Vs[16][36];
    float acc = 0.f;
    for (int b = 0; b < Bn; b++) {
        __syncthreads();
        {
            int idx = threadIdx.x;           // 0..255 -> 2 loads each (512 elems)
            int r = idx >> 5, c = idx & 31;
            Us[r][c] = g_U[((size_t)b*Nn + s0 + r)*Dn + c];
            Vs[r][c] = g_V[((size_t)b*Nn + t0 + r)*Dn + c];
            idx += 256; r = idx >> 5; c = idx & 31;
            Us[r][c] = g_U[((size_t)b*Nn + s0 + r)*Dn + c];
            Vs[r][c] = g_V[((size_t)b*Nn + t0 + r)*Dn + c];
        }
        __syncthreads();
        #pragma unroll
        for (int q = 0; q < 8; q++) {
            float4 u = *(const float4*)&Us[ty][4*q];
            float4 v = *(const float4*)&Vs[tx][4*q];
            acc += u.x*v.x + u.y*v.y + u.z*v.z + u.w*v.w;
        }
    }
    g_C[(s0+ty)*Nn + (t0+tx)] = acc;
}

// ---------------- Kernel C: fused per-edge MLP (2 batches/block, f32x2) ------
// grid = (N, B/2), block = 128. Thread e handles edge p = i*127+e for b0, b1.
__global__ void __launch_bounds__(128) kC(
        const float* __restrict__ inp,
        const float* __restrict__ W2, const float* __restrict__ b2,
        const float* __restrict__ W3, const float* __restrict__ b3,
        const float* __restrict__ Wf1, const float* __restrict__ bf1,
        const float* __restrict__ g1, const float* __restrict__ be1,
        float* __restrict__ outEdges) {
    const int i   = blockIdx.x;
    const int b0  = blockIdx.y * 2;
    const int b1b = b0 + 1;
    const int e   = threadIdx.x;

    __shared__ __align__(16) float W2t[32*32];    // W2t[c*32+k] = W2[k*32+c]
    __shared__ __align__(16) float W3t[33*32];    // W3t[c*32+k] = W3[k*33+c]
    __shared__ float b2s[32], b3s[33];
    __shared__ float us0[32], us1[32], xs0[32], xs1[32];
    __shared__ float red0[Gn*33], red1[Gn*33];
    __shared__ float red2a[4*32], red2b[4*32];

    for (int idx = e; idx < 1024; idx += 128) {
        int c = idx >> 5, k = idx & 31;
        W2t[idx] = W2[k*32 + c];
    }
    for (int idx = e; idx < 1056; idx += 128) {
        int c = idx >> 5, k = idx & 31;
        W3t[idx] = W3[k*33 + c];
    }
    if (e < 32) {
        b2s[e] = b2[e];
        us0[e] = g_U[((size_t)b0*Nn + i)*Dn + e];
        us1[e] = g_U[((size_t)b1b*Nn + i)*Dn + e];
        xs0[e] = inp[((size_t)b0*Nn + i)*Dn + e];
        xs1[e] = inp[((size_t)b1b*Nn + i)*Dn + e];
    }
    if (e < 33) b3s[e] = b3[e];
    __syncthreads();

    if (e < Gn) {
        const int t = e + (e >= i);
        const int p = i * Gn + e;

        // LN scale/shift inline (depends on p only; shared by both batches)
        const float inv = 1.0f / 2048.0f;
        float m  = (g_sumU[i] + g_sumV[t]) * inv;
        float e2 = (g_sumU2[i] + g_sumV2[t] + 2.0f * g_C[i*Nn + t]) * inv;
        float sc = rsqrtf(e2 - m*m + EPSf) * g1[p];
        float sh = be1[p] - m * sc;

        const float4* vr0 = (const float4*)(g_V + ((size_t)b0*Nn + t)*Dn);
        const float4* vr1 = (const float4*)(g_V + ((size_t)b1b*Nn + t)*Dn);

        // activations (leaky(LN(h))) packed along k: A[j] = (a[2j], a[2j+1])
        u64 A0[16], A1[16];
        #pragma unroll
        for (int q = 0; q < 8; q++) {
            float4 v0 = vr0[q];
            float4 v1 = vr1[q];
            float p00 = leaky((us0[4*q+0] + v0.x) * sc + sh);
            float p01 = leaky((us0[4*q+1] + v0.y) * sc + sh);
            float p02 = leaky((us0[4*q+2] + v0.z) * sc + sh);
            float p03 = leaky((us0[4*q+3] + v0.w) * sc + sh);
            float p10 = leaky((us1[4*q+0] + v1.x) * sc + sh);
            float p11 = leaky((us1[4*q+1] + v1.y) * sc + sh);
            float p12 = leaky((us1[4*q+2] + v1.z) * sc + sh);
            float p13 = leaky((us1[4*q+3] + v1.w) * sc + sh);
            A0[2*q+0] = pk2(p00, p01);
            A0[2*q+1] = pk2(p02, p03);
            A1[2*q+0] = pk2(p10, p11);
            A1[2*q+1] = pk2(p12, p13);
        }

        // Layer 2: packed fma, one weight load serves both batches
        u64 A20[16], A21[16];
        float carry0 = 0.f, carry1 = 0.f;
        #pragma unroll 2
        for (int c = 0; c < 32; c++) {
            const ulonglong2* wr = (const ulonglong2*)(W2t + c*32);
            u64 acc0a = 0ull, acc0b = 0ull, acc1a = 0ull, acc1b = 0ull;
            #pragma unroll
            for (int j = 0; j < 4; j++) {
                ulonglong2 wA = wr[2*j];
                ulonglong2 wB = wr[2*j+1];
                acc0a = ffma2(A0[4*j+0], wA.x, acc0a);
                acc0b = ffma2(A0[4*j+1], wA.y, acc0b);
                acc1a = ffma2(A1[4*j+0], wA.x, acc1a);
                acc1b = ffma2(A1[4*j+1], wA.y, acc1b);
                acc0a = ffma2(A0[4*j+2], wB.x, acc0a);
                acc0b = ffma2(A0[4*j+3], wB.y, acc0b);
                acc1a = ffma2(A1[4*j+2], wB.x, acc1a);
                acc1b = ffma2(A1[4*j+3], wB.y, acc1b);
            }
            float s0 = leaky(b2s[c] + hadd2(acc0a) + hadd2(acc0b));
            float s1 = leaky(b2s[c] + hadd2(acc1a) + hadd2(acc1b));
            if (c & 1) {
                A20[c>>1] = pk2(carry0, s0);
                A21[c>>1] = pk2(carry1, s1);
            } else { carry0 = s0; carry1 = s1; }
        }

        // Layer 3 channel 0 -> edge gates
        float edge0, edge1;
        {
            const ulonglong2* wr = (const ulonglong2*)(W3t);
            u64 acc0a = 0ull, acc0b = 0ull, acc1a = 0ull, acc1b = 0ull;
            #pragma unroll
            for (int j = 0; j < 4; j++) {
                ulonglong2 wA = wr[2*j];
                ulonglong2 wB = wr[2*j+1];
                acc0a = ffma2(A20[4*j+0], wA.x, acc0a);
                acc0b = ffma2(A20[4*j+1], wA.y, acc0b);
                acc1a = ffma2(A21[4*j+0], wA.x, acc1a);
                acc1b = ffma2(A21[4*j+1], wA.y, acc1b);
                acc0a = ffma2(A20[4*j+2], wB.x, acc0a);
                acc0b = ffma2(A20[4*j+3], wB.y, acc0b);
                acc1a = ffma2(A21[4*j+2], wB.x, acc1a);
                acc1b = ffma2(A21[4*j+3], wB.y, acc1b);
            }
            float s0 = b3s[0] + hadd2(acc0a) + hadd2(acc0b);
            float s1 = b3s[0] + hadd2(acc1a) + hadd2(acc1b);
            edge0 = 1.0f / (1.0f + __expf(-s0));
            edge1 = 1.0f / (1.0f + __expf(-s1));
        }
        outEdges[(size_t)b0  * Pn + p] = edge0;
        outEdges[(size_t)b1b * Pn + p] = edge1;

        // Layer 3 channels 1..32 -> weighted messages
        #pragma unroll 2
        for (int c = 1; c < 33; c++) {
            const ulonglong2* wr = (const ulonglong2*)(W3t + c*32);
            u64 acc0a = 0ull, acc0b = 0ull, acc1a = 0ull, acc1b = 0ull;
            #pragma unroll
            for (int j = 0; j < 4; j++) {
                ulonglong2 wA = wr[2*j];
                ulonglong2 wB = wr[2*j+1];
                acc0a = ffma2(A20[4*j+0], wA.x, acc0a);
                acc0b = ffma2(A20[4*j+1], wA.y, acc0b);
                acc1a = ffma2(A21[4*j+0], wA.x, acc1a);
                acc1b = ffma2(A21[4*j+1], wA.y, acc1b);
                acc0a = ffma2(A20[4*j+2], wB.x, acc0a);
                acc0b = ffma2(A20[4*j+3], wB.y, acc0b);
                acc1a = ffma2(A21[4*j+2], wB.x, acc1a);
                acc1b = ffma2(A21[4*j+3], wB.y, acc1b);
            }
            float s0 = b3s[c] + hadd2(acc0a) + hadd2(acc0b);
            float s1 = b3s[c] + hadd2(acc1a) + hadd2(acc1b);
            red0[e*33 + (c-1)] = edge0 * s0;
            red1[e*33 + (c-1)] = edge1 * s1;
        }
    }
    __syncthreads();

    // stage 1: quarter q sums rows [q*32, min(q*32+32,127)) for channel c
    {
        const int q = e >> 5;
        const int c = e & 31;
        const int r0 = q * 32;
        const int r1 = (q == 3) ? Gn : r0 + 32;
        float s0 = 0.f, s1 = 0.f;
        for (int r = r0; r < r1; r++) {
            s0 += red0[r*33 + c];
            s1 += red1[r*33 + c];
        }
        red2a[q*32 + c] = s0;
        red2b[q*32 + c] = s1;
    }
    __syncthreads();

    if (e < HFn) {
        float acc = bf1[e];
        #pragma unroll
        for (int k = 0; k < 32; k++) acc += xs0[k] * Wf1[k*HFn + e];
        #pragma unroll
        for (int k = 0; k < 32; k++) {
            float aggk = red2a[k] + red2a[32+k] + red2a[64+k] + red2a[96+k];
            acc += aggk * Wf1[(32+k)*HFn + e];
        }
        g_f[((size_t)b0*Nn + i)*HFn + e] = acc;
    } else if (e >= 64 && e < 64 + HFn) {
        const int c = e - 64;
        float acc = bf1[c];
        #pragma unroll
        for (int k = 0; k < 32; k++) acc += xs1[k] * Wf1[k*HFn + c];
        #pragma unroll
        for (int k = 0; k < 32; k++) {
            float aggk = red2b[k] + red2b[32+k] + red2b[64+k] + red2b[96+k];
            acc += aggk * Wf1[(32+k)*HFn + c];
        }
        g_f[((size_t)b1b*Nn + i)*HFn + c] = acc;
    }
}

// ---------------- Kernel E1: partial column stats of f (64 blocks) -----------
__global__ void kE1() {
    __shared__ float rs[128], rs2[128];
    const int tid = threadIdx.x;            // 128
    const int j = tid & 15, g = tid >> 4;   // 8 groups
    const int r0 = blockIdx.x * 128;
    float s = 0.f, s2 = 0.f;
    #pragma unroll
    for (int m = 0; m < 16; m++) {
        float v = g_f[(size_t)(r0 + g*16 + m)*HFn + j];
        s += v; s2 += v * v;
    }
    rs[tid] = s; rs2[tid] = s2;
    __syncthreads();
    for (int st = 64; st >= 16; st >>= 1) {
        if (tid < st) { rs[tid] += rs[tid+st]; rs2[tid] += rs2[tid+st]; }
        __syncthreads();
    }
    if (tid < 16) {
        g_part[blockIdx.x*32 + tid]      = rs[tid];
        g_part[blockIdx.x*32 + 16 + tid] = rs2[tid];
    }
}

// ---------------- Kernel E2: finalize LN params -------------------------------
__global__ void kE2(const float* __restrict__ gf, const float* __restrict__ bef) {
    const int tid = threadIdx.x;   // 32
    __shared__ float sh[32];
    float v = 0.f;
    #pragma unroll 4
    for (int b = 0; b < 64; b++) v += g_part[b*32 + tid];
    sh[tid] = v;
    __syncthreads();
    if (tid < 16) {
        const float invR = 1.0f / 8192.0f;
        float mean = sh[tid] * invR;
        float var  = sh[16+tid] * invR - mean * mean;
        float sc = rsqrtf(var + EPSf) * gf[tid];
        g_lnp[tid]      = sc;
        g_lnp[16 + tid] = bef[tid] - mean * sc;
    }
}

// ---------------- Kernel F: final MLP -> out ---------------------------------
__global__ void kF(const float* __restrict__ Wf2, const float* __restrict__ bf2,
                   float* __restrict__ outp) {
    __shared__ __align__(16) float Wf2s[16*32];
    __shared__ float lnsc[16], lnsh[16], bf2s[32];
    const int tid = threadIdx.x;
    for (int idx = tid; idx < 16*32; idx += 256) Wf2s[idx] = Wf2[idx];
    if (tid < 16) { lnsc[tid] = g_lnp[tid]; lnsh[tid] = g_lnp[16+tid]; }
    if (tid < 32) bf2s[tid] = bf2[tid];
    __syncthreads();

    const int r = blockIdx.x * 256 + tid;   // 0..8191
    float gq[16];
    #pragma unroll
    for (int j = 0; j < 16; j++) {
        float v = g_f[(size_t)r*HFn + j];
        gq[j] = leaky(v * lnsc[j] + lnsh[j]);
    }
    float4* op = (float4*)(outp + (size_t)r * Dn);
    #pragma unroll
    for (int q = 0; q < 8; q++) {
        float o[4];
        #pragma unroll
        for (int u = 0; u < 4; u++) {
            int c = 4*q + u;
            float acc = bf2s[c];
            #pragma unroll
            for (int j = 0; j < 16; j++) acc += gq[j] * Wf2s[j*32 + c];
            o[u] = acc;
        }
        op[q] = make_float4(o[0], o[1], o[2], o[3]);
    }
}

// ---------------- launch ------------------------------------------------------
extern "C" void kernel_launch(void* const* d_in, const int* in_sizes, int n_in,
                              void* d_out, int out_size) {
    const float* inp = (const float*)d_in[0];
    const float* W1  = (const float*)d_in[3];
    const float* b1  = (const float*)d_in[4];
    const float* g1  = (const float*)d_in[5];
    const float* be1 = (const float*)d_in[6];
    const float* W2  = (const float*)d_in[7];
    const float* b2  = (const float*)d_in[8];
    const float* W3  = (const float*)d_in[9];
    const float* b3  = (const float*)d_in[10];
    const float* Wf1 = (const float*)d_in[11];
    const float* bf1 = (const float*)d_in[12];
    const float* gf  = (const float*)d_in[13];
    const float* bef = (const float*)d_in[14];
    const float* Wf2 = (const float*)d_in[15];
    const float* bf2 = (const float*)d_in[16];

    float* outEdges = (float*)d_out;                       // (B, P)
    float* outFeat  = (float*)d_out + (size_t)Bn * Pn;     // (B, N, D)

    kA<<<Nn, 64>>>(inp, W1, b1);
    kB<<<dim3(8, 8), 256>>>();
    kC<<<dim3(Nn, Bn/2), 128>>>(inp, W2, b2, W3, b3, Wf1, bf1, g1, be1, outEdges);
    kE1<<<64, 128>>>();
    kE2<<<1, 32>>>(gf, bef);
    kF<<<32, 256>>>(Wf2, bf2, outFeat);
}

// round 6
// speedup vs baseline: 1.3160x; 1.3160x over previous
#include <cuda_runtime.h>
#include <math.h>

#define Bn 64
#define Nn 128
#define Dn 32
#define Gn 127              // N-1
#define Pn (Nn*(Nn-1))      // 16256
#define HFn 16
#define EPSf 1e-5f

// ---------------- scratch (static device globals; no allocation) -------------
__device__ float g_U[Bn*Nn*Dn];      // U'[b][n][c] = x@W1_top + b1
__device__ float g_V[Bn*Nn*Dn];      // V [b][n][c] = x@W1_bot
__device__ float g_sumU[Nn], g_sumU2[Nn], g_sumV[Nn], g_sumV2[Nn];
__device__ float g_C[Nn*Nn];         // C[s][t] = sum_{b,c} U'[b,s,c]*V[b,t,c]
__device__ float g_f[Bn*Nn*HFn];     // pre-LN features of final MLP
__device__ float g_part[64*32];      // kE1 partials
__device__ float g_lnp[2*HFn];       // [0:16) scale, [16:32) shift

__device__ __forceinline__ float leaky(float x) { return x > 0.f ? x : 0.01f * x; }

// ---------------- Kernel A: per-node projections + per-node stats ------------
__global__ void kA(const float* __restrict__ inp, const float* __restrict__ W1,
                   const float* __restrict__ b1) {
    const int n = blockIdx.x;
    const int b = threadIdx.x;     // 0..63
    __shared__ __align__(16) float W1t[32*64];   // W1t[c*64 + k] = W1[k*32 + c]
    __shared__ float red[64*4];
    for (int idx = b; idx < 2048; idx += 64) {
        int k = idx & 63, c = idx >> 6;
        W1t[c*64 + k] = W1[k*32 + c];
    }
    __syncthreads();

    float x[32];
    const float4* xp = (const float4*)(inp + ((size_t)b*Nn + n)*Dn);
    #pragma unroll
    for (int q = 0; q < 8; q++) {
        float4 v = xp[q];
        x[4*q+0]=v.x; x[4*q+1]=v.y; x[4*q+2]=v.z; x[4*q+3]=v.w;
    }
    float su=0.f, su2=0.f, sv=0.f, sv2=0.f;
    float* Uo = g_U + ((size_t)b*Nn + n)*Dn;
    float* Vo = g_V + ((size_t)b*Nn + n)*Dn;
    #pragma unroll 4
    for (int c = 0; c < 32; c++) {
        const float4* wr = (const float4*)(W1t + c*64);
        float u = b1[c];
        float v = 0.f;
        #pragma unroll
        for (int j = 0; j < 8; j++) {
            float4 wu = wr[j];
            float4 wv = wr[8 + j];
            u += x[4*j+0]*wu.x + x[4*j+1]*wu.y + x[4*j+2]*wu.z + x[4*j+3]*wu.w;
            v += x[4*j+0]*wv.x + x[4*j+1]*wv.y + x[4*j+2]*wv.z + x[4*j+3]*wv.w;
        }
        Uo[c] = u; Vo[c] = v;
        su += u; su2 += u*u; sv += v; sv2 += v*v;
    }
    red[b] = su; red[64+b] = su2; red[128+b] = sv; red[192+b] = sv2;
    __syncthreads();
    for (int s = 32; s > 0; s >>= 1) {
        if (b < s) {
            red[b]     += red[b+s];
            red[64+b]  += red[64+b+s];
            red[128+b] += red[128+b+s];
            red[192+b] += red[192+b+s];
        }
        __syncthreads();
    }
    if (b == 0) {
        g_sumU[n]  = red[0];
        g_sumU2[n] = red[64];
        g_sumV[n]  = red[128];
        g_sumV2[n] = red[192];
    }
}

// ---------------- Kernel B: cross term C[s,t], 128x128, K = 64*32 ------------
__global__ void kB() {
    const int t0 = blockIdx.x * 16;
    const int s0 = blockIdx.y * 16;
    const int tx = threadIdx.x & 15;
    const int ty = threadIdx.x >> 4;
    __shared__ __align__(16) float Us[16][36];
    __shared__ __align__(16) float Vs[16][36];
    float acc = 0.f;
    for (int b = 0; b < Bn; b++) {
        __syncthreads();
        {
            int idx = threadIdx.x;
            int r = idx >> 5, c = idx & 31;
            Us[r][c] = g_U[((size_t)b*Nn + s0 + r)*Dn + c];
            Vs[r][c] = g_V[((size_t)b*Nn + t0 + r)*Dn + c];
            idx += 256; r = idx >> 5; c = idx & 31;
            Us[r][c] = g_U[((size_t)b*Nn + s0 + r)*Dn + c];
            Vs[r][c] = g_V[((size_t)b*Nn + t0 + r)*Dn + c];
        }
        __syncthreads();
        #pragma unroll
        for (int q = 0; q < 8; q++) {
            float4 u = *(const float4*)&Us[ty][4*q];
            float4 v = *(const float4*)&Vs[tx][4*q];
            acc += u.x*v.x + u.y*v.y + u.z*v.z + u.w*v.w;
        }
    }
    g_C[(s0+ty)*Nn + (t0+tx)] = acc;
}

// ---------------- Kernel C: fused per-edge MLP, GEMM2 eliminated -------------
// grid = (N, B/4), block = 128, dynamic smem. Thread e = edge, 4 batches.
struct SC {
    float W2s[1024];     // W2[k][c] original layout
    float W3s[1056];     // W3[c][33] original layout
    float w3c0[32];      // W3[c][0]
    float b2s[32];
    float b3s[36];
    float us[4][32];
    float xs[4][32];
    float gw[4][4];      // [warp][batch] gate partial sums
    float zs[4*32];      // z[b][c]
    float aggs[4*32];    // agg[b][d]
    float red[4][32*127];// red[b][c*127 + e] = gate*a2  (k-major, conflict-free)
};

__global__ void __launch_bounds__(128) kC(
        const float* __restrict__ inp,
        const float* __restrict__ W2, const float* __restrict__ b2,
        const float* __restrict__ W3, const float* __restrict__ b3,
        const float* __restrict__ Wf1, const float* __restrict__ bf1,
        const float* __restrict__ g1, const float* __restrict__ be1,
        float* __restrict__ outEdges) {
    extern __shared__ __align__(16) char smem_raw[];
    SC* S = (SC*)smem_raw;

    const int i  = blockIdx.x;
    const int bb = blockIdx.y * 4;
    const int e  = threadIdx.x;      // 0..127
    const int warp = e >> 5;
    const int lane = e & 31;

    // ---- init loads ----
    for (int idx = e; idx < 1024; idx += 128) S->W2s[idx] = W2[idx];
    for (int idx = e; idx < 1056; idx += 128) S->W3s[idx] = W3[idx];
    if (e < 32) { S->w3c0[e] = W3[e*33]; S->b2s[e] = b2[e]; }
    if (e < 33) S->b3s[e] = b3[e];
    {
        const int b = e >> 5, k = e & 31;
        S->us[b][k] = g_U[((size_t)(bb+b)*Nn + i)*Dn + k];
        S->xs[b][k] = inp[((size_t)(bb+b)*Nn + i)*Dn + k];
    }
    __syncthreads();

    float gate0 = 0.f, gate1 = 0.f, gate2 = 0.f, gate3 = 0.f;

    if (e < Gn) {
        const int t = e + (e >= i);
        const int p = i * Gn + e;

        // LN scale/shift (depends on p only; shared by all batches)
        const float inv = 1.0f / 2048.0f;
        float m  = (g_sumU[i] + g_sumV[t]) * inv;
        float e2 = (g_sumU2[i] + g_sumV2[t] + 2.0f * g_C[i*Nn + t]) * inv;
        float sc = rsqrtf(e2 - m*m + EPSf) * g1[p];
        float sh = be1[p] - m * sc;

        const float4* vr0 = (const float4*)(g_V + ((size_t)(bb+0)*Nn + t)*Dn);
        const float4* vr1 = (const float4*)(g_V + ((size_t)(bb+1)*Nn + t)*Dn);
        const float4* vr2 = (const float4*)(g_V + ((size_t)(bb+2)*Nn + t)*Dn);
        const float4* vr3 = (const float4*)(g_V + ((size_t)(bb+3)*Nn + t)*Dn);

        // GEMM1 accumulators, outer-product over k (weights broadcast LDS.128)
        float acc0[32], acc1[32], acc2[32], acc3[32];
        #pragma unroll
        for (int c = 0; c < 32; c++) { acc0[c]=0.f; acc1[c]=0.f; acc2[c]=0.f; acc3[c]=0.f; }

        #pragma unroll
        for (int q = 0; q < 8; q++) {
            float4 v0 = vr0[q], v1 = vr1[q], v2 = vr2[q], v3 = vr3[q];
            float a0[4], a1[4], a2_[4], a3[4];
            a0[0]=leaky((S->us[0][4*q+0]+v0.x)*sc+sh); a0[1]=leaky((S->us[0][4*q+1]+v0.y)*sc+sh);
            a0[2]=leaky((S->us[0][4*q+2]+v0.z)*sc+sh); a0[3]=leaky((S->us[0][4*q+3]+v0.w)*sc+sh);
            a1[0]=leaky((S->us[1][4*q+0]+v1.x)*sc+sh); a1[1]=leaky((S->us[1][4*q+1]+v1.y)*sc+sh);
            a1[2]=leaky((S->us[1][4*q+2]+v1.z)*sc+sh); a1[3]=leaky((S->us[1][4*q+3]+v1.w)*sc+sh);
            a2_[0]=leaky((S->us[2][4*q+0]+v2.x)*sc+sh); a2_[1]=leaky((S->us[2][4*q+1]+v2.y)*sc+sh);
            a2_[2]=leaky((S->us[2][4*q+2]+v2.z)*sc+sh); a2_[3]=leaky((S->us[2][4*q+3]+v2.w)*sc+sh);
            a3[0]=leaky((S->us[3][4*q+0]+v3.x)*sc+sh); a3[1]=leaky((S->us[3][4*q+1]+v3.y)*sc+sh);
            a3[2]=leaky((S->us[3][4*q+2]+v3.z)*sc+sh); a3[3]=leaky((S->us[3][4*q+3]+v3.w)*sc+sh);

            #pragma unroll
            for (int j = 0; j < 4; j++) {
                const int k = 4*q + j;
                const float4* wrow = (const float4*)(S->W2s + k*32);
                #pragma unroll
                for (int c4 = 0; c4 < 8; c4++) {
                    float4 w = wrow[c4];
                    acc0[c4*4+0] += a0[j]*w.x;  acc0[c4*4+1] += a0[j]*w.y;
                    acc0[c4*4+2] += a0[j]*w.z;  acc0[c4*4+3] += a0[j]*w.w;
                    acc1[c4*4+0] += a1[j]*w.x;  acc1[c4*4+1] += a1[j]*w.y;
                    acc1[c4*4+2] += a1[j]*w.z;  acc1[c4*4+3] += a1[j]*w.w;
                    acc2[c4*4+0] += a2_[j]*w.x; acc2[c4*4+1] += a2_[j]*w.y;
                    acc2[c4*4+2] += a2_[j]*w.z; acc2[c4*4+3] += a2_[j]*w.w;
                    acc3[c4*4+0] += a3[j]*w.x;  acc3[c4*4+1] += a3[j]*w.y;
                    acc3[c4*4+2] += a3[j]*w.z;  acc3[c4*4+3] += a3[j]*w.w;
                }
            }
        }

        // bias + leaky, then gate dot (layer-3 column 0)
        float ga0 = S->b3s[0], ga1 = S->b3s[0], ga2 = S->b3s[0], ga3 = S->b3s[0];
        #pragma unroll
        for (int c = 0; c < 32; c++) {
            float bc = S->b2s[c];
            acc0[c] = leaky(acc0[c] + bc);
            acc1[c] = leaky(acc1[c] + bc);
            acc2[c] = leaky(acc2[c] + bc);
            acc3[c] = leaky(acc3[c] + bc);
            float w0 = S->w3c0[c];
            ga0 += acc0[c]*w0; ga1 += acc1[c]*w0; ga2 += acc2[c]*w0; ga3 += acc3[c]*w0;
        }
        gate0 = 1.0f / (1.0f + __expf(-ga0));
        gate1 = 1.0f / (1.0f + __expf(-ga1));
        gate2 = 1.0f / (1.0f + __expf(-ga2));
        gate3 = 1.0f / (1.0f + __expf(-ga3));
        outEdges[(size_t)(bb+0)*Pn + p] = gate0;
        outEdges[(size_t)(bb+1)*Pn + p] = gate1;
        outEdges[(size_t)(bb+2)*Pn + p] = gate2;
        outEdges[(size_t)(bb+3)*Pn + p] = gate3;

        // store g*a2 for z reduction (k-major: conflict-free writes & reads)
        #pragma unroll
        for (int c = 0; c < 32; c++) {
            S->red[0][c*Gn + e] = gate0 * acc0[c];
            S->red[1][c*Gn + e] = gate1 * acc1[c];
            S->red[2][c*Gn + e] = gate2 * acc2[c];
            S->red[3][c*Gn + e] = gate3 * acc3[c];
        }
    }

    // warp-reduce gate sums (thread 127 contributes 0)
    {
        float v0 = gate0, v1 = gate1, v2 = gate2, v3 = gate3;
        #pragma unroll
        for (int s = 16; s > 0; s >>= 1) {
            v0 += __shfl_xor_sync(0xffffffffu, v0, s);
            v1 += __shfl_xor_sync(0xffffffffu, v1, s);
            v2 += __shfl_xor_sync(0xffffffffu, v2, s);
            v3 += __shfl_xor_sync(0xffffffffu, v3, s);
        }
        if (lane == 0) {
            S->gw[warp][0] = v0; S->gw[warp][1] = v1;
            S->gw[warp][2] = v2; S->gw[warp][3] = v3;
        }
    }
    __syncthreads();

    // z reduction: thread (b = e>>5, c = e&31) sums 127 edges
    {
        const int b = e >> 5, c = e & 31;
        const float* rr = &S->red[b][c*Gn];
        float s0 = 0.f, s1 = 0.f, s2 = 0.f, s3 = 0.f;
        int r = 0;
        #pragma unroll 4
        for (; r + 4 <= Gn; r += 4) {
            s0 += rr[r]; s1 += rr[r+1]; s2 += rr[r+2]; s3 += rr[r+3];
        }
        for (; r < Gn; r++) s0 += rr[r];
        S->zs[b*32 + c] = (s0 + s1) + (s2 + s3);
    }
    __syncthreads();

    // agg[b][d] = G[b]*b3[d+1] + sum_c z[b][c] * W3[c][d+1]
    {
        const int b = e >> 5, d = e & 31;
        float G = S->gw[0][b] + S->gw[1][b] + S->gw[2][b] + S->gw[3][b];
        float acc = G * S->b3s[d+1];
        const float* zb = &S->zs[b*32];
        #pragma unroll
        for (int c = 0; c < 32; c++) acc += zb[c] * S->W3s[c*33 + (d+1)];
        S->aggs[b*32 + d] = acc;
    }
    __syncthreads();

    // f = [x, agg] @ Wf1 + bf1
    if (e < 64) {
        const int b = e >> 4, c = e & 15;
        float acc = bf1[c];
        #pragma unroll
        for (int k = 0; k < 32; k++) acc += S->xs[b][k] * Wf1[k*HFn + c];
        #pragma unroll
        for (int k = 0; k < 32; k++) acc += S->aggs[b*32 + k] * Wf1[(32+k)*HFn + c];
        g_f[((size_t)(bb+b)*Nn + i)*HFn + c] = acc;
    }
}

// ---------------- Kernel E1: partial column stats of f (64 blocks) -----------
__global__ void kE1() {
    __shared__ float rs[128], rs2[128];
    const int tid = threadIdx.x;            // 128
    const int j = tid & 15, g = tid >> 4;   // 8 groups
    const int r0 = blockIdx.x * 128;
    float s = 0.f, s2 = 0.f;
    #pragma unroll
    for (int m = 0; m < 16; m++) {
        float v = g_f[(size_t)(r0 + g*16 + m)*HFn + j];
        s += v; s2 += v * v;
    }
    rs[tid] = s; rs2[tid] = s2;
    __syncthreads();
    for (int st = 64; st >= 16; st >>= 1) {
        if (tid < st) { rs[tid] += rs[tid+st]; rs2[tid] += rs2[tid+st]; }
        __syncthreads();
    }
    if (tid < 16) {
        g_part[blockIdx.x*32 + tid]      = rs[tid];
        g_part[blockIdx.x*32 + 16 + tid] = rs2[tid];
    }
}

// ---------------- Kernel E2: finalize LN params -------------------------------
__global__ void kE2(const float* __restrict__ gf, const float* __restrict__ bef) {
    const int tid = threadIdx.x;   // 32
    __shared__ float sh[32];
    float v = 0.f;
    #pragma unroll 4
    for (int b = 0; b < 64; b++) v += g_part[b*32 + tid];
    sh[tid] = v;
    __syncthreads();
    if (tid < 16) {
        const float invR = 1.0f / 8192.0f;
        float mean = sh[tid] * invR;
        float var  = sh[16+tid] * invR - mean * mean;
        float sc = rsqrtf(var + EPSf) * gf[tid];
        g_lnp[tid]      = sc;
        g_lnp[16 + tid] = bef[tid] - mean * sc;
    }
}

// ---------------- Kernel F: final MLP -> out ---------------------------------
__global__ void kF(const float* __restrict__ Wf2, const float* __restrict__ bf2,
                   float* __restrict__ outp) {
    __shared__ __align__(16) float Wf2s[16*32];
    __shared__ float lnsc[16], lnsh[16], bf2s[32];
    const int tid = threadIdx.x;
    for (int idx = tid; idx < 16*32; idx += 256) Wf2s[idx] = Wf2[idx];
    if (tid < 16) { lnsc[tid] = g_lnp[tid]; lnsh[tid] = g_lnp[16+tid]; }
    if (tid < 32) bf2s[tid] = bf2[tid];
    __syncthreads();

    const int r = blockIdx.x * 256 + tid;   // 0..8191
    float gq[16];
    #pragma unroll
    for (int j = 0; j < 16; j++) {
        float v = g_f[(size_t)r*HFn + j];
        gq[j] = leaky(v * lnsc[j] + lnsh[j]);
    }
    float4* op = (float4*)(outp + (size_t)r * Dn);
    #pragma unroll
    for (int q = 0; q < 8; q++) {
        float o[4];
        #pragma unroll
        for (int u = 0; u < 4; u++) {
            int c = 4*q + u;
            float acc = bf2s[c];
            #pragma unroll
            for (int j = 0; j < 16; j++) acc += gq[j] * Wf2s[j*32 + c];
            o[u] = acc;
        }
        op[q] = make_float4(o[0], o[1], o[2], o[3]);
    }
}

// ---------------- launch ------------------------------------------------------
extern "C" void kernel_launch(void* const* d_in, const int* in_sizes, int n_in,
                              void* d_out, int out_size) {
    const float* inp = (const float*)d_in[0];
    const float* W1  = (const float*)d_in[3];
    const float* b1  = (const float*)d_in[4];
    const float* g1  = (const float*)d_in[5];
    const float* be1 = (const float*)d_in[6];
    const float* W2  = (const float*)d_in[7];
    const float* b2  = (const float*)d_in[8];
    const float* W3  = (const float*)d_in[9];
    const float* b3  = (const float*)d_in[10];
    const float* Wf1 = (const float*)d_in[11];
    const float* bf1 = (const float*)d_in[12];
    const float* gf  = (const float*)d_in[13];
    const float* bef = (const float*)d_in[14];
    const float* Wf2 = (const float*)d_in[15];
    const float* bf2 = (const float*)d_in[16];

    float* outEdges = (float*)d_out;                       // (B, P)
    float* outFeat  = (float*)d_out + (size_t)Bn * Pn;     // (B, N, D)

    const int smemC = (int)sizeof(SC);
    cudaFuncSetAttribute(kC, cudaFuncAttributeMaxDynamicSharedMemorySize, smemC);

    kA<<<Nn, 64>>>(inp, W1, b1);
    kB<<<dim3(8, 8), 256>>>();
    kC<<<dim3(Nn, Bn/4), 128, smemC>>>(inp, W2, b2, W3, b3, Wf1, bf1, g1, be1, outEdges);
    kE1<<<64, 128>>>();
    kE2<<<1, 32>>>(gf, bef);
    kF<<<32, 256>>>(Wf2, bf2, outFeat);
}

// round 7
// speedup vs baseline: 1.4978x; 1.1382x over previous
#include <cuda_runtime.h>
#include <math.h>

#define Bn 64
#define Nn 128
#define Dn 32
#define Gn 127              // N-1
#define Pn (Nn*(Nn-1))      // 16256
#define HFn 16
#define EPSf 1e-5f

// ---------------- scratch (static device globals; no allocation) -------------
__device__ float g_U[Bn*Nn*Dn];      // U'[b][n][c] = x@W1_top + b1
__device__ float g_V[Bn*Nn*Dn];      // V [b][n][c] = x@W1_bot
__device__ float g_sumU[Nn], g_sumU2[Nn], g_sumV[Nn], g_sumV2[Nn];
__device__ float g_C[Nn*Nn];         // C[s][t] = sum_{b,c} U'[b,s,c]*V[b,t,c]
__device__ float g_f[Bn*Nn*HFn];     // pre-LN features of final MLP
__device__ float g_fsum[HFn], g_fsum2[HFn];
 
__device__ __forceinline__ float leaky(float x) { return x > 0.f ? x : 0.01f * x; }

// ---------------- Kernel A: per-node projections + stats + zeroing -----------
__global__ void kA(const float* __restrict__ inp, const float* __restrict__ W1,
                   const float* __restrict__ b1) {
    const int n = blockIdx.x;
    const int b = threadIdx.x;     // 0..63
    __shared__ __align__(16) float W1t[32*64];   // W1t[c*64 + k] = W1[k*32 + c]
    __shared__ float red[64*4];

    // zero g_C slice + f-stat accumulators (consumed by later kernels)
    g_C[n*128 + b*2]     = 0.f;
    g_C[n*128 + b*2 + 1] = 0.f;
    if (n == 0 && b < HFn) { g_fsum[b] = 0.f; g_fsum2[b] = 0.f; }

    for (int idx = b; idx < 2048; idx += 64) {
        int k = idx & 63, c = idx >> 6;
        W1t[c*64 + k] = W1[k*32 + c];
    }
    __syncthreads();

    float x[32];
    const float4* xp = (const float4*)(inp + ((size_t)b*Nn + n)*Dn);
    #pragma unroll
    for (int q = 0; q < 8; q++) {
        float4 v = xp[q];
        x[4*q+0]=v.x; x[4*q+1]=v.y; x[4*q+2]=v.z; x[4*q+3]=v.w;
    }
    float su=0.f, su2=0.f, sv=0.f, sv2=0.f;
    float* Uo = g_U + ((size_t)b*Nn + n)*Dn;
    float* Vo = g_V + ((size_t)b*Nn + n)*Dn;
    #pragma unroll 4
    for (int c = 0; c < 32; c++) {
        const float4* wr = (const float4*)(W1t + c*64);
        float u = b1[c];
        float v = 0.f;
        #pragma unroll
        for (int j = 0; j < 8; j++) {
            float4 wu = wr[j];
            float4 wv = wr[8 + j];
            u += x[4*j+0]*wu.x + x[4*j+1]*wu.y + x[4*j+2]*wu.z + x[4*j+3]*wu.w;
            v += x[4*j+0]*wv.x + x[4*j+1]*wv.y + x[4*j+2]*wv.z + x[4*j+3]*wv.w;
        }
        Uo[c] = u; Vo[c] = v;
        su += u; su2 += u*u; sv += v; sv2 += v*v;
    }
    red[b] = su; red[64+b] = su2; red[128+b] = sv; red[192+b] = sv2;
    __syncthreads();
    for (int s = 32; s > 0; s >>= 1) {
        if (b < s) {
            red[b]     += red[b+s];
            red[64+b]  += red[64+b+s];
            red[128+b] += red[128+b+s];
            red[192+b] += red[192+b+s];
        }
        __syncthreads();
    }
    if (b == 0) {
        g_sumU[n]  = red[0];
        g_sumU2[n] = red[64];
        g_sumV[n]  = red[128];
        g_sumV2[n] = red[192];
    }
}

// ---------------- Kernel B: cross term C[s,t], K-split x8, REDG --------------
// grid = (8,8,8), block = 256 (16x16 tile; z = slice of 8 batches)
__global__ void kB() {
    const int t0 = blockIdx.x * 16;
    const int s0 = blockIdx.y * 16;
    const int bz = blockIdx.z * 8;
    const int tx = threadIdx.x & 15;
    const int ty = threadIdx.x >> 4;
    __shared__ __align__(16) float Us[16][36];
    __shared__ __align__(16) float Vs[16][36];
    float acc = 0.f;
    for (int b = bz; b < bz + 8; b++) {
        __syncthreads();
        {
            int idx = threadIdx.x;
            int r = idx >> 5, c = idx & 31;
            Us[r][c] = g_U[((size_t)b*Nn + s0 + r)*Dn + c];
            Vs[r][c] = g_V[((size_t)b*Nn + t0 + r)*Dn + c];
            idx += 256; r = idx >> 5; c = idx & 31;
            Us[r][c] = g_U[((size_t)b*Nn + s0 + r)*Dn + c];
            Vs[r][c] = g_V[((size_t)b*Nn + t0 + r)*Dn + c];
        }
        __syncthreads();
        #pragma unroll
        for (int q = 0; q < 8; q++) {
            float4 u = *(const float4*)&Us[ty][4*q];
            float4 v = *(const float4*)&Vs[tx][4*q];
            acc += u.x*v.x + u.y*v.y + u.z*v.z + u.w*v.w;
        }
    }
    atomicAdd(&g_C[(s0+ty)*Nn + (t0+tx)], acc);
}

// ---------------- Kernel C: fused per-edge MLP, V staged in smem -------------
// grid = (N, B/4), block = 128, dynamic smem.
struct SC {
    float W2s[1024];     // W2[k][c] original layout
    float W3s[1056];     // W3[c][33] original layout
    float w3c0[32];      // W3[c][0]
    float b2s[32];
    float b3s[36];
    float us[4][32];
    float xs[4][32];
    float gw[4][4];      // [warp][batch] gate partial sums
    float zs[4*32];      // z[b][c]
    float aggs[4*32];    // agg[b][d]
    union {
        float4 Vt[4][8][128];   // staged V: [batch][k-chunk][t]
        float  red[4][32*Gn];   // gate*a2, k-major (written after V is dead)
    } u;
};

__global__ void __launch_bounds__(128) kC(
        const float* __restrict__ inp,
        const float* __restrict__ W2, const float* __restrict__ b2,
        const float* __restrict__ W3, const float* __restrict__ b3,
        const float* __restrict__ Wf1, const float* __restrict__ bf1,
        const float* __restrict__ g1, const float* __restrict__ be1,
        float* __restrict__ outEdges) {
    extern __shared__ __align__(16) char smem_raw[];
    SC* S = (SC*)smem_raw;

    const int i  = blockIdx.x;
    const int bb = blockIdx.y * 4;
    const int e  = threadIdx.x;      // 0..127
    const int warp = e >> 5;
    const int lane = e & 31;

    // ---- init loads ----
    for (int idx = e; idx < 1024; idx += 128) S->W2s[idx] = W2[idx];
    for (int idx = e; idx < 1056; idx += 128) S->W3s[idx] = W3[idx];
    if (e < 32) { S->w3c0[e] = W3[e*33]; S->b2s[e] = b2[e]; }
    if (e < 33) S->b3s[e] = b3[e];
    {
        const int b = e >> 5, k = e & 31;
        S->us[b][k] = g_U[((size_t)(bb+b)*Nn + i)*Dn + k];
        S->xs[b][k] = inp[((size_t)(bb+b)*Nn + i)*Dn + k];
    }
    // ---- stage V tile (4 batches x 128 rows x 32), coalesced ----
    {
        const float4* gsrc = (const float4*)(g_V + (size_t)bb*Nn*Dn);
        #pragma unroll
        for (int m = 0; m < 32; m++) {
            int f = m*128 + e;                 // 0..4095 float4s, coalesced
            int b = f >> 10, rem = f & 1023, t = rem >> 3, q = rem & 7;
            S->u.Vt[b][q][t] = gsrc[f];
        }
    }
    __syncthreads();

    float acc0[32], acc1[32], acc2[32], acc3[32];
    float gate0 = 0.f, gate1 = 0.f, gate2 = 0.f, gate3 = 0.f;

    if (e < Gn) {
        const int t = e + (e >= i);
        const int p = i * Gn + e;

        // LN scale/shift (depends on p only; shared by all batches)
        const float inv = 1.0f / 2048.0f;
        float m  = (g_sumU[i] + g_sumV[t]) * inv;
        float e2 = (g_sumU2[i] + g_sumV2[t] + 2.0f * g_C[i*Nn + t]) * inv;
        float sc = rsqrtf(e2 - m*m + EPSf) * g1[p];
        float sh = be1[p] - m * sc;

        #pragma unroll
        for (int c = 0; c < 32; c++) { acc0[c]=0.f; acc1[c]=0.f; acc2[c]=0.f; acc3[c]=0.f; }

        #pragma unroll
        for (int q = 0; q < 8; q++) {
            float4 v0 = S->u.Vt[0][q][t];
            float4 v1 = S->u.Vt[1][q][t];
            float4 v2 = S->u.Vt[2][q][t];
            float4 v3 = S->u.Vt[3][q][t];
            float a0[4], a1[4], a2_[4], a3[4];
            a0[0]=leaky((S->us[0][4*q+0]+v0.x)*sc+sh); a0[1]=leaky((S->us[0][4*q+1]+v0.y)*sc+sh);
            a0[2]=leaky((S->us[0][4*q+2]+v0.z)*sc+sh); a0[3]=leaky((S->us[0][4*q+3]+v0.w)*sc+sh);
            a1[0]=leaky((S->us[1][4*q+0]+v1.x)*sc+sh); a1[1]=leaky((S->us[1][4*q+1]+v1.y)*sc+sh);
            a1[2]=leaky((S->us[1][4*q+2]+v1.z)*sc+sh); a1[3]=leaky((S->us[1][4*q+3]+v1.w)*sc+sh);
            a2_[0]=leaky((S->us[2][4*q+0]+v2.x)*sc+sh); a2_[1]=leaky((S->us[2][4*q+1]+v2.y)*sc+sh);
            a2_[2]=leaky((S->us[2][4*q+2]+v2.z)*sc+sh); a2_[3]=leaky((S->us[2][4*q+3]+v2.w)*sc+sh);
            a3[0]=leaky((S->us[3][4*q+0]+v3.x)*sc+sh); a3[1]=leaky((S->us[3][4*q+1]+v3.y)*sc+sh);
            a3[2]=leaky((S->us[3][4*q+2]+v3.z)*sc+sh); a3[3]=leaky((S->us[3][4*q+3]+v3.w)*sc+sh);

            #pragma unroll
            for (int j = 0; j < 4; j++) {
                const int k = 4*q + j;
                const float4* wrow = (const float4*)(S->W2s + k*32);
                #pragma unroll
                for (int c4 = 0; c4 < 8; c4++) {
                    float4 w = wrow[c4];
                    acc0[c4*4+0] += a0[j]*w.x;  acc0[c4*4+1] += a0[j]*w.y;
                    acc0[c4*4+2] += a0[j]*w.z;  acc0[c4*4+3] += a0[j]*w.w;
                    acc1[c4*4+0] += a1[j]*w.x;  acc1[c4*4+1] += a1[j]*w.y;
                    acc1[c4*4+2] += a1[j]*w.z;  acc1[c4*4+3] += a1[j]*w.w;
                    acc2[c4*4+0] += a2_[j]*w.x; acc2[c4*4+1] += a2_[j]*w.y;
                    acc2[c4*4+2] += a2_[j]*w.z; acc2[c4*4+3] += a2_[j]*w.w;
                    acc3[c4*4+0] += a3[j]*w.x;  acc3[c4*4+1] += a3[j]*w.y;
                    acc3[c4*4+2] += a3[j]*w.z;  acc3[c4*4+3] += a3[j]*w.w;
                }
            }
        }

        // bias + leaky, then gate dot (layer-3 column 0)
        float ga0 = S->b3s[0], ga1 = S->b3s[0], ga2 = S->b3s[0], ga3 = S->b3s[0];
        #pragma unroll
        for (int c = 0; c < 32; c++) {
            float bc = S->b2s[c];
            acc0[c] = leaky(acc0[c] + bc);
            acc1[c] = leaky(acc1[c] + bc);
            acc2[c] = leaky(acc2[c] + bc);
            acc3[c] = leaky(acc3[c] + bc);
            float w0 = S->w3c0[c];
            ga0 += acc0[c]*w0; ga1 += acc1[c]*w0; ga2 += acc2[c]*w0; ga3 += acc3[c]*w0;
        }
        gate0 = 1.0f / (1.0f + __expf(-ga0));
        gate1 = 1.0f / (1.0f + __expf(-ga1));
        gate2 = 1.0f / (1.0f + __expf(-ga2));
        gate3 = 1.0f / (1.0f + __expf(-ga3));
        outEdges[(size_t)(bb+0)*Pn + p] = gate0;
        outEdges[(size_t)(bb+1)*Pn + p] = gate1;
        outEdges[(size_t)(bb+2)*Pn + p] = gate2;
        outEdges[(size_t)(bb+3)*Pn + p] = gate3;
    }

    __syncthreads();   // all V reads done -> safe to overwrite union with red

    if (e < Gn) {
        #pragma unroll
        for (int c = 0; c < 32; c++) {
            S->u.red[0][c*Gn + e] = gate0 * acc0[c];
            S->u.red[1][c*Gn + e] = gate1 * acc1[c];
            S->u.red[2][c*Gn + e] = gate2 * acc2[c];
            S->u.red[3][c*Gn + e] = gate3 * acc3[c];
        }
    }

    // warp-reduce gate sums (thread 127 contributes 0)
    {
        float v0 = gate0, v1 = gate1, v2 = gate2, v3 = gate3;
        #pragma unroll
        for (int s = 16; s > 0; s >>= 1) {
            v0 += __shfl_xor_sync(0xffffffffu, v0, s);
            v1 += __shfl_xor_sync(0xffffffffu, v1, s);
            v2 += __shfl_xor_sync(0xffffffffu, v2, s);
            v3 += __shfl_xor_sync(0xffffffffu, v3, s);
        }
        if (lane == 0) {
            S->gw[warp][0] = v0; S->gw[warp][1] = v1;
            S->gw[warp][2] = v2; S->gw[warp][3] = v3;
        }
    }
    __syncthreads();

    // z reduction: thread (b = e>>5, c = e&31) sums 127 edges (conflict-free)
    {
        const int b = e >> 5, c = e & 31;
        const float* rr = &S->u.red[b][c*Gn];
        float s0 = 0.f, s1 = 0.f, s2 = 0.f, s3 = 0.f;
        int r = 0;
        #pragma unroll 4
        for (; r + 4 <= Gn; r += 4) {
            s0 += rr[r]; s1 += rr[r+1]; s2 += rr[r+2]; s3 += rr[r+3];
        }
        for (; r < Gn; r++) s0 += rr[r];
        S->zs[b*32 + c] = (s0 + s1) + (s2 + s3);
    }
    __syncthreads();

    // agg[b][d] = G[b]*b3[d+1] + sum_c z[b][c] * W3[c][d+1]
    {
        const int b = e >> 5, d = e & 31;
        float G = S->gw[0][b] + S->gw[1][b] + S->gw[2][b] + S->gw[3][b];
        float acc = G * S->b3s[d+1];
        const float* zb = &S->zs[b*32];
        #pragma unroll
        for (int c = 0; c < 32; c++) acc += zb[c] * S->W3s[c*33 + (d+1)];
        S->aggs[b*32 + d] = acc;
    }
    __syncthreads();

    // f = [x, agg] @ Wf1 + bf1 ; accumulate column stats for the final LN
    if (e < 64) {
        const int b = e >> 4, c = e & 15;
        float acc = bf1[c];
        #pragma unroll
        for (int k = 0; k < 32; k++) acc += S->xs[b][k] * Wf1[k*HFn + c];
        #pragma unroll
        for (int k = 0; k < 32; k++) acc += S->aggs[b*32 + k] * Wf1[(32+k)*HFn + c];
        g_f[((size_t)(bb+b)*Nn + i)*HFn + c] = acc;
        atomicAdd(&g_fsum[c],  acc);
        atomicAdd(&g_fsum2[c], acc*acc);
    }
}

// ---------------- Kernel F: final LN (inline params) + MLP -> out -------------
__global__ void kF(const float* __restrict__ gf, const float* __restrict__ bef,
                   const float* __restrict__ Wf2, const float* __restrict__ bf2,
                   float* __restrict__ outp) {
    __shared__ __align__(16) float Wf2s[16*32];
    __shared__ float lnsc[16], lnsh[16], bf2s[32];
    const int tid = threadIdx.x;
    for (int idx = tid; idx < 16*32; idx += 256) Wf2s[idx] = Wf2[idx];
    if (tid < 16) {
        const float invR = 1.0f / 8192.0f;
        float mean = g_fsum[tid] * invR;
        float var  = g_fsum2[tid] * invR - mean * mean;
        float sc = rsqrtf(var + EPSf) * gf[tid];
        lnsc[tid] = sc;
        lnsh[tid] = bef[tid] - mean * sc;
    }
    if (tid < 32) bf2s[tid] = bf2[tid];
    __syncthreads();

    const int r = blockIdx.x * 256 + tid;   // 0..8191
    float gq[16];
    #pragma unroll
    for (int j = 0; j < 16; j++) {
        float v = g_f[(size_t)r*HFn + j];
        gq[j] = leaky(v * lnsc[j] + lnsh[j]);
    }
    float4* op = (float4*)(outp + (size_t)r * Dn);
    #pragma unroll
    for (int q = 0; q < 8; q++) {
        float o[4];
        #pragma unroll
        for (int u = 0; u < 4; u++) {
            int c = 4*q + u;
            float acc = bf2s[c];
            #pragma unroll
            for (int j = 0; j < 16; j++) acc += gq[j] * Wf2s[j*32 + c];
            o[u] = acc;
        }
        op[q] = make_float4(o[0], o[1], o[2], o[3]);
    }
}

// ---------------- launch ------------------------------------------------------
extern "C" void kernel_launch(void* const* d_in, const int* in_sizes, int n_in,
                              void* d_out, int out_size) {
    const float* inp = (const float*)d_in[0];
    const float* W1  = (const float*)d_in[3];
    const float* b1  = (const float*)d_in[4];
    const float* g1  = (const float*)d_in[5];
    const float* be1 = (const float*)d_in[6];
    const float* W2  = (const float*)d_in[7];
    const float* b2  = (const float*)d_in[8];
    const float* W3  = (const float*)d_in[9];
    const float* b3  = (const float*)d_in[10];
    const float* Wf1 = (const float*)d_in[11];
    const float* bf1 = (const float*)d_in[12];
    const float* gf  = (const float*)d_in[13];
    const float* bef = (const float*)d_in[14];
    const float* Wf2 = (const float*)d_in[15];
    const float* bf2 = (const float*)d_in[16];

    float* outEdges = (float*)d_out;                       // (B, P)
    float* outFeat  = (float*)d_out + (size_t)Bn * Pn;     // (B, N, D)

    const int smemC = (int)sizeof(SC);
    cudaFuncSetAttribute(kC, cudaFuncAttributeMaxDynamicSharedMemorySize, smemC);

    kA<<<Nn, 64>>>(inp, W1, b1);
    kB<<<dim3(8, 8, 8), 256>>>();
    kC<<<dim3(Nn, Bn/4), 128, smemC>>>(inp, W2, b2, W3, b3, Wf1, bf1, g1, be1, outEdges);
    kF<<<32, 256>>>(gf, bef, Wf2, bf2, outFeat);
}